// round 16
// baseline (speedup 1.0000x reference)
#include <cuda_runtime.h>
#include <cuda_fp16.h>
#include <stdint.h>
#include <math.h>

#define BB   2048
#define TT   48
#define HH   512
#define EE   256
#define VV   128
#define ENCC 1024
#define H3   1536

// ===================== stable-ISA PTX helpers (sm_80+) ======================
__device__ __forceinline__ uint32_t smem_u32(const void* p) {
    uint32_t a;
    asm("{ .reg .u64 t; cvta.to.shared.u64 t, %1; cvt.u32.u64 %0, t; }" : "=r"(a) : "l"(p));
    return a;
}
__device__ __forceinline__ void cp_async16(uint32_t dst, const void* src) {
    asm volatile("cp.async.cg.shared.global [%0], [%1], 16;" :: "r"(dst), "l"(src));
}
#define CP_COMMIT() asm volatile("cp.async.commit_group;" ::: "memory")
#define CP_WAIT1()  asm volatile("cp.async.wait_group 1;" ::: "memory")

__device__ __forceinline__ void ldsm_x4(uint32_t* r, uint32_t addr) {
    asm volatile("ldmatrix.sync.aligned.m8n8.x4.shared.b16 {%0,%1,%2,%3}, [%4];"
                 : "=r"(r[0]), "=r"(r[1]), "=r"(r[2]), "=r"(r[3]) : "r"(addr));
}
__device__ __forceinline__ void mma16816(float* d, const uint32_t* a, const uint32_t* b) {
    asm volatile("mma.sync.aligned.m16n8k16.row.col.f32.f16.f16.f32 "
                 "{%0,%1,%2,%3}, {%4,%5,%6,%7}, {%8,%9}, {%0,%1,%2,%3};"
                 : "+f"(d[0]), "+f"(d[1]), "+f"(d[2]), "+f"(d[3])
                 : "r"(a[0]), "r"(a[1]), "r"(a[2]), "r"(a[3]), "r"(b[0]), "r"(b[1]));
}

// ===================== device scratch (no allocations) ======================
__device__ __align__(16) float g_proj[VV * H3];          // layer-1 x-gates per vocab id (fp32)
__device__ __align__(16) float g_h1 [BB * HH];           // fp32 states
__device__ __align__(16) float g_h2 [BB * HH];

// fp16 gate pre-activations (GEMM outputs)
__device__ __align__(16) __half g_in1h[BB * H3];
__device__ __align__(16) __half g_xg2h[BB * H3];
__device__ __align__(16) __half g_in2h[BB * H3];

// activations: fp16 (A operands)
__device__ __align__(16) __half g_h1h[BB * HH];
__device__ __align__(16) __half g_h2h[BB * HH];
__device__ __align__(16) __half g_seqh[(size_t)BB * TT * HH];
__device__ __align__(16) __half g_ench[BB * ENCC];
__device__ __align__(16) __half g_embh[VV * EE];

// weights: fp16, transposed [N,K] (B operands)
__device__ __align__(16) __half g_k1h [H3 * EE];
__device__ __align__(16) __half g_rk1h[H3 * HH];
__device__ __align__(16) __half g_k2h [H3 * HH];
__device__ __align__(16) __half g_rk2h[H3 * HH];
__device__ __align__(16) __half g_wi1h[HH * ENCC];
__device__ __align__(16) __half g_wi2h[HH * ENCC];
__device__ __align__(16) __half g_wvh [VV * HH];

// ===================== prep: transpose / convert ============================
__global__ __launch_bounds__(256)
void tsplit_kernel(const float* __restrict__ W, __half* __restrict__ Th, int K, int N) {
    __shared__ float s[32][33];
    int n0 = blockIdx.x * 32, k0 = blockIdx.y * 32;
    int tx = threadIdx.x & 31, ty = threadIdx.x >> 5;
#pragma unroll
    for (int i = 0; i < 32; i += 8)
        s[ty + i][tx] = W[(size_t)(k0 + ty + i) * N + n0 + tx];
    __syncthreads();
#pragma unroll
    for (int i = 0; i < 32; i += 8)
        Th[(size_t)(n0 + ty + i) * K + k0 + tx] = __float2half(s[tx][ty + i]);
}

__global__ __launch_bounds__(256)
void tsplit3_kernel(const float* __restrict__ W0, __half* __restrict__ Th0,
                    const float* __restrict__ W1, __half* __restrict__ Th1,
                    const float* __restrict__ W2, __half* __restrict__ Th2) {
    const float* W = (blockIdx.z == 0) ? W0 : (blockIdx.z == 1) ? W1 : W2;
    __half* Th = (blockIdx.z == 0) ? Th0 : (blockIdx.z == 1) ? Th1 : Th2;
    const int K = HH, N = H3;
    __shared__ float s[32][33];
    int n0 = blockIdx.x * 32, k0 = blockIdx.y * 32;
    int tx = threadIdx.x & 31, ty = threadIdx.x >> 5;
#pragma unroll
    for (int i = 0; i < 32; i += 8)
        s[ty + i][tx] = W[(size_t)(k0 + ty + i) * N + n0 + tx];
    __syncthreads();
#pragma unroll
    for (int i = 0; i < 32; i += 8)
        Th[(size_t)(n0 + ty + i) * K + k0 + tx] = __float2half(s[tx][ty + i]);
}

__global__ __launch_bounds__(256)
void split_kernel(const float* __restrict__ src, __half* __restrict__ dh, int n4) {
    int i = blockIdx.x * 256 + threadIdx.x;
    if (i >= n4) return;
    float4 v = ((const float4*)src)[i];
    ((__half2*)dh)[2*i]   = __halves2half2(__float2half(v.x), __float2half(v.y));
    ((__half2*)dh)[2*i+1] = __halves2half2(__float2half(v.z), __float2half(v.w));
}

// ===================== mma.sync single-pass fp16 GEMM =======================
// C = Ah @ Bh^T, fp32 accumulate. 3-stage cp.async pipeline, XOR swizzle,
// one __syncthreads per K-chunk. Output: fp32 C and/or fp16 Ch (bias added).
#define TILE_B    (128 * 32 * 2)         // 8192 bytes per operand tile
#define STAGE_B   (2 * TILE_B)           // A, B = 16384
#define SMEM_DYN  (3 * STAGE_B)          // 49152 bytes

#define SWOFF(r, u) ((r) * 64 + (((u) ^ (((r) >> 1) & 3)) * 16))

struct TJob {
    const __half *Ah;        // [M,K]
    const __half *Bh;        // [N,K]
    const float* bias;       // nullable
    float* C;                // nullable fp32 output
    __half *Ch;              // nullable fp16 output
};

__global__ __launch_bounds__(256, 2)
void tc_gemm(TJob j0, TJob j1, TJob j2, int K, int N) {
    extern __shared__ __align__(16) char smem[];
    const TJob& jb = (blockIdx.z == 0) ? j0 : (blockIdx.z == 1) ? j1 : j2;
    const uint32_t sb = smem_u32(smem);
    const int tid = threadIdx.x;
    const int lane = tid & 31, warp = tid >> 5;
    const int wm = warp & 1, wn = warp >> 1;
    const int bm = blockIdx.y * 128, bn = blockIdx.x * 128;
    const int kch = K / 32;

    auto issue = [&](int c) {
        const int k0 = c * 32;
        const uint32_t st = sb + (c % 3) * STAGE_B;
#pragma unroll
        for (int i = 0; i < 4; i++) {
            const int tile = i >> 1;
            const int w = (i & 1) ? (tid + 256) & 511 : tid;
            const int row = w >> 2, u = w & 3;
            const __half* src = (tile == 0) ? jb.Ah : jb.Bh;
            const int roff = (tile == 0) ? bm : bn;
            cp_async16(st + tile * TILE_B + SWOFF(row, u),
                       src + (size_t)(roff + row) * K + k0 + u * 8);
        }
    };

    float acc[4][4][4];
#pragma unroll
    for (int i = 0; i < 4; i++)
#pragma unroll
        for (int j = 0; j < 4; j++)
#pragma unroll
            for (int q = 0; q < 4; q++) acc[i][j][q] = 0.f;

    const int arow = lane & 15, au = (lane >> 4);
    const int brow4 = lane & 7;
    const int bu = (lane >> 3) & 1;
    const int bnsel = ((lane >> 4) & 1) * 8;

    issue(0); CP_COMMIT();
    issue(1); CP_COMMIT();

    for (int c = 0; c < kch; c++) {
        CP_WAIT1();
        __syncthreads();
        if (c + 2 < kch) issue(c + 2);
        CP_COMMIT();

        const uint32_t st = sb + (c % 3) * STAGE_B;
        const uint32_t ah = st, bh = st + TILE_B;
#pragma unroll
        for (int kt = 0; kt < 2; kt++) {
            uint32_t afh[4][4], bfh[2][4];
#pragma unroll
            for (int mt = 0; mt < 4; mt++) {
                int r = wm * 64 + mt * 16 + arow;
                ldsm_x4(afh[mt], ah + SWOFF(r, kt * 2 + au));
            }
#pragma unroll
            for (int p = 0; p < 2; p++) {
                int r = wn * 32 + p * 16 + bnsel + brow4;
                ldsm_x4(bfh[p], bh + SWOFF(r, kt * 2 + bu));
            }
#pragma unroll
            for (int mt = 0; mt < 4; mt++)
#pragma unroll
                for (int nt = 0; nt < 4; nt++)
                    mma16816(acc[mt][nt], afh[mt], &bfh[nt >> 1][(nt & 1) * 2]);
        }
    }

    const int quad = lane >> 2, pair = lane & 3;
#pragma unroll
    for (int mt = 0; mt < 4; mt++) {
#pragma unroll
        for (int h = 0; h < 2; h++) {
            int row = bm + wm * 64 + mt * 16 + quad + h * 8;
#pragma unroll
            for (int nt = 0; nt < 4; nt++) {
                int col = bn + wn * 32 + nt * 8 + pair * 2;
                float v0 = acc[mt][nt][2 * h]     + (jb.bias ? jb.bias[col]     : 0.f);
                float v1 = acc[mt][nt][2 * h + 1] + (jb.bias ? jb.bias[col + 1] : 0.f);
                if (jb.C)
                    *(float2*)(jb.C + (size_t)row * N + col) = make_float2(v0, v1);
                if (jb.Ch)
                    *(__half2*)(jb.Ch + (size_t)row * N + col) =
                        __halves2half2(__float2half(v0), __float2half(v1));
            }
        }
    }
}

// ===================== GRU gate updates =====================================
__device__ __forceinline__ float sigm_(float x) { return 1.f / (1.f + expf(-x)); }

__device__ __forceinline__ float4 load_h4(const __half* p) {
    float2 a = __half22float2(*(const __half2*)p);
    float2 b = __half22float2(*(const __half2*)(p + 2));
    return make_float4(a.x, a.y, b.x, b.y);
}

__device__ __forceinline__ void gate4(const float4& xz, const float4& xr, const float4& xh,
                                      const float4& rz, const float4& rr, const float4& rh,
                                      float4& hv) {
    float z, r, hg;
    z = sigm_(xz.x + rz.x); r = sigm_(xr.x + rr.x); hg = tanhf(xh.x + r * rh.x); hv.x = z * hv.x + (1.f - z) * hg;
    z = sigm_(xz.y + rz.y); r = sigm_(xr.y + rr.y); hg = tanhf(xh.y + r * rh.y); hv.y = z * hv.y + (1.f - z) * hg;
    z = sigm_(xz.z + rz.z); r = sigm_(xr.z + rr.z); hg = tanhf(xh.z + r * rh.z); hv.z = z * hv.z + (1.f - z) * hg;
    z = sigm_(xz.w + rz.w); r = sigm_(xr.w + rr.w); hg = tanhf(xh.w + r * rh.w); hv.w = z * hv.w + (1.f - z) * hg;
}
__device__ __forceinline__ void store_h4(const float4& hv, __half* ph) {
    *(__half2*)(ph)     = __halves2half2(__float2half(hv.x), __float2half(hv.y));
    *(__half2*)(ph + 2) = __halves2half2(__float2half(hv.z), __float2half(hv.w));
}

// layer-1-only bootstrap update (t=0)
__global__ __launch_bounds__(256)
void gru_step1(const float* __restrict__ proj, const int* __restrict__ tgt, int t1,
               const __half* __restrict__ in1h, float* __restrict__ h1,
               __half* __restrict__ h1h) {
    int idx = blockIdx.x * 256 + threadIdx.x;
    int b = idx >> 7;
    int j = (idx & 127) * 4;
    size_t hidx = (size_t)b * HH + j;
    int tok = tgt[b * TT + t1];
    if (tok != 0) {
        float4 hv = *(float4*)(h1 + hidx);
        const float* xg = proj + (size_t)tok * H3;
        const __half* in = in1h + (size_t)b * H3;
        gate4(*(const float4*)(xg + j), *(const float4*)(xg + HH + j), *(const float4*)(xg + 2*HH + j),
              load_h4(in + j), load_h4(in + HH + j), load_h4(in + 2*HH + j), hv);
        *(float4*)(h1 + hidx) = hv;
        store_h4(hv, h1h + hidx);
    }
}

// fused per-step update: layer-2 at t2 (+ seq emit), layer-1 at t1 = t2+1
__global__ __launch_bounds__(256)
void gru_step_full(const float* __restrict__ proj, const int* __restrict__ tgt,
                   int t1, const __half* __restrict__ in1h, float* __restrict__ h1,
                   __half* __restrict__ h1h,
                   int t2, const __half* __restrict__ xg2h, const __half* __restrict__ in2h,
                   float* __restrict__ h2, __half* __restrict__ h2h,
                   __half* __restrict__ seqh) {
    int idx = blockIdx.x * 256 + threadIdx.x;
    int b = idx >> 7;
    int j = (idx & 127) * 4;
    size_t hidx = (size_t)b * HH + j;

    {
        float4 hv = *(float4*)(h2 + hidx);
        if (tgt[b * TT + t2] != 0) {
            const __half* xg = xg2h + (size_t)b * H3;
            const __half* in = in2h + (size_t)b * H3;
            gate4(load_h4(xg + j), load_h4(xg + HH + j), load_h4(xg + 2*HH + j),
                  load_h4(in + j), load_h4(in + HH + j), load_h4(in + 2*HH + j), hv);
            *(float4*)(h2 + hidx) = hv;
            store_h4(hv, h2h + hidx);
        }
        size_t so = (size_t)b * (TT * HH) + (size_t)t2 * HH + j;
        store_h4(hv, seqh + so);   // output == state, even masked
    }
    if (t1 < TT) {
        int tok = tgt[b * TT + t1];
        if (tok != 0) {
            float4 hv = *(float4*)(h1 + hidx);
            const float* xg = proj + (size_t)tok * H3;
            const __half* in = in1h + (size_t)b * H3;
            gate4(*(const float4*)(xg + j), *(const float4*)(xg + HH + j), *(const float4*)(xg + 2*HH + j),
                  load_h4(in + j), load_h4(in + HH + j), load_h4(in + 2*HH + j), hv);
            *(float4*)(h1 + hidx) = hv;
            store_h4(hv, h1h + hidx);
        }
    }
}

// ===================== softmax over V=128 ===================================
__global__ __launch_bounds__(256)
void softmax_kernel(float* __restrict__ out) {
    int row  = blockIdx.x * 8 + (threadIdx.x >> 5);
    int lane = threadIdx.x & 31;
    float* p = out + (size_t)row * VV + lane * 4;
    float4 v = *(float4*)p;
    float m = fmaxf(fmaxf(v.x, v.y), fmaxf(v.z, v.w));
#pragma unroll
    for (int o = 16; o > 0; o >>= 1) m = fmaxf(m, __shfl_xor_sync(0xffffffffu, m, o));
    v.x = expf(v.x - m); v.y = expf(v.y - m); v.z = expf(v.z - m); v.w = expf(v.w - m);
    float s = v.x + v.y + v.z + v.w;
#pragma unroll
    for (int o = 16; o > 0; o >>= 1) s += __shfl_xor_sync(0xffffffffu, s, o);
    float inv = 1.f / s;
    v.x *= inv; v.y *= inv; v.z *= inv; v.w *= inv;
    *(float4*)p = v;
}

// ===================== launch ===============================================
static void* sym(const void* s) { void* p; cudaGetSymbolAddress(&p, s); return p; }

extern "C" void kernel_launch(void* const* d_in, const int* in_sizes, int n_in,
                              void* d_out, int out_size) {
    const int*   tgt = (const int*)  d_in[0];
    const float* enc = (const float*)d_in[1];
    const float* Wi1 = (const float*)d_in[2];
    const float* Wi2 = (const float*)d_in[3];
    const float* emb = (const float*)d_in[4];
    const float* k1  = (const float*)d_in[5];
    const float* rk1 = (const float*)d_in[6];
    const float* b1  = (const float*)d_in[7];
    const float* k2  = (const float*)d_in[8];
    const float* rk2 = (const float*)d_in[9];
    const float* b2  = (const float*)d_in[10];
    const float* Wv  = (const float*)d_in[11];
    const float* bv  = (const float*)d_in[12];
    float* out = (float*)d_out;

    float* proj = (float*)sym(g_proj);
    float* h1  = (float*)sym(g_h1);   float* h2  = (float*)sym(g_h2);
    __half *in1h=(__half*)sym(g_in1h), *xg2h=(__half*)sym(g_xg2h), *in2h=(__half*)sym(g_in2h);
    __half *h1h=(__half*)sym(g_h1h);
    __half *h2h=(__half*)sym(g_h2h);
    __half *sqh=(__half*)sym(g_seqh);
    __half *ench=(__half*)sym(g_ench);
    __half *embh=(__half*)sym(g_embh);
    __half *k1h=(__half*)sym(g_k1h);
    __half *rk1h=(__half*)sym(g_rk1h);
    __half *k2h=(__half*)sym(g_k2h);
    __half *rk2h=(__half*)sym(g_rk2h);
    __half *wi1h=(__half*)sym(g_wi1h);
    __half *wi2h=(__half*)sym(g_wi2h);
    __half *wvh=(__half*)sym(g_wvh);

    cudaFuncSetAttribute(tc_gemm, cudaFuncAttributeMaxDynamicSharedMemorySize, SMEM_DYN);

    dim3 blk(256);

    // ---- prep ----
    tsplit_kernel<<<dim3(HH/32, ENCC/32),blk>>>(Wi1, wi1h, ENCC, HH);
    tsplit_kernel<<<dim3(HH/32, ENCC/32),blk>>>(Wi2, wi2h, ENCC, HH);
    split_kernel<<<(BB*ENCC/4 + 255)/256, blk>>>(enc, ench, BB*ENCC/4);
    tsplit_kernel<<<dim3(H3/32, EE/32),  blk>>>(k1,  k1h,  EE,   H3);
    split_kernel<<<(VV*EE/4 + 255)/256,   blk>>>(emb, embh, VV*EE/4);

    // h0 init: fp32 states + fp16 copies
    {
        TJob a = {ench, wi1h, nullptr, h1, h1h};
        TJob b = {ench, wi2h, nullptr, h2, h2h};
        tc_gemm<<<dim3(HH/128, BB/128, 2), blk, SMEM_DYN>>>(a, b, a, ENCC, HH);
    }
    tsplit3_kernel<<<dim3(H3/32, HH/32, 3), blk>>>(rk1, rk1h, k2, k2h, rk2, rk2h);
    tsplit_kernel<<<dim3(VV/32, HH/32),  blk>>>(Wv,  wvh,  HH,   VV);

    // proj = emb_table @ k1 + b1[0]  (fp32, V=128 rows only)
    {
        TJob a = {embh, k1h, b1, proj, nullptr};
        tc_gemm<<<dim3(H3/128, 1, 1), blk, SMEM_DYN>>>(a, a, a, EE, H3);
    }
    // inner1(t=0) = h1 @ rk1 + b1[1]  (fp16 out)
    {
        TJob a = {h1h, rk1h, b1 + H3, nullptr, in1h};
        tc_gemm<<<dim3(H3/128, BB/128, 1), blk, SMEM_DYN>>>(a, a, a, HH, H3);
    }
    const int gblocks = BB * HH / 4 / 256;  // 1024
    gru_step1<<<gblocks, blk>>>(proj, tgt, 0, in1h, h1, h1h);

    // ---- 48 steps: one packed 3-job GEMM + one fused gate kernel ----
    for (int t = 0; t < TT; t++) {
        TJob a = {h1h, k2h,  b2,      nullptr, xg2h};
        TJob b = {h2h, rk2h, b2 + H3, nullptr, in2h};
        TJob c = {h1h, rk1h, b1 + H3, nullptr, in1h};
        int nz = (t == TT - 1) ? 2 : 3;   // in1 for t=TT never consumed
        tc_gemm<<<dim3(H3/128, BB/128, nz), blk, SMEM_DYN>>>(a, b, c, HH, H3);
        gru_step_full<<<gblocks, blk>>>(proj, tgt, t + 1, in1h, h1, h1h,
                                        t, xg2h, in2h, h2, h2h, sqh);
    }

    // ---- logits = seq2 @ Wv + bv, then softmax (in d_out) ----
    {
        TJob a = {sqh, wvh, bv, out, nullptr};
        tc_gemm<<<dim3(VV/128, (BB*TT)/128, 1), blk, SMEM_DYN>>>(a, a, a, HH, VV);
    }
    softmax_kernel<<<(BB*TT)/8, blk>>>(out);
}